// round 16
// baseline (speedup 1.0000x reference)
#include <cuda_runtime.h>
#include <cuda_bf16.h>
#include <math.h>

#define S_DIM   4096
#define D_DIM   4096
#define R_DIM   1024
#define DFF_DIM 11008

#define THRESH_UP   0.4f
#define THRESH_GATE 0.4f
#define THRESH_DOWN 0.1f

// ---------------- device global scratch (allocation is banned) -------------
__device__ float g_oup[(size_t)S_DIM * DFF_DIM];                  // o_up fp32
__device__ __align__(16) __nv_bfloat16 g_bxu_h[(size_t)S_DIM * R_DIM];
__device__ __align__(16) __nv_bfloat16 g_bxu_m[(size_t)S_DIM * R_DIM];
__device__ __align__(16) __nv_bfloat16 g_bxu_l[(size_t)S_DIM * R_DIM];
__device__ __align__(16) __nv_bfloat16 g_bxg_h[(size_t)S_DIM * R_DIM];
__device__ __align__(16) __nv_bfloat16 g_bxg_m[(size_t)S_DIM * R_DIM];
__device__ __align__(16) __nv_bfloat16 g_bxg_l[(size_t)S_DIM * R_DIM];
__device__ __align__(16) __nv_bfloat16 g_atu_h[(size_t)R_DIM * DFF_DIM];
__device__ __align__(16) __nv_bfloat16 g_atu_m[(size_t)R_DIM * DFF_DIM];
__device__ __align__(16) __nv_bfloat16 g_atu_l[(size_t)R_DIM * DFF_DIM];
__device__ __align__(16) __nv_bfloat16 g_atg_h[(size_t)R_DIM * DFF_DIM];
__device__ __align__(16) __nv_bfloat16 g_atg_m[(size_t)R_DIM * DFF_DIM];
__device__ __align__(16) __nv_bfloat16 g_atg_l[(size_t)R_DIM * DFF_DIM];
__device__ __align__(16) __nv_bfloat16 g_wtd_hi[(size_t)DFF_DIM * D_DIM];
__device__ __align__(16) __nv_bfloat16 g_wtd_lo[(size_t)DFF_DIM * D_DIM];
__device__ __align__(16) __nv_bfloat16 g_hh[(size_t)S_DIM * DFF_DIM];
__device__ __align__(16) __nv_bfloat16 g_hl[(size_t)S_DIM * DFF_DIM];

enum { EPI_NONE = 0, EPI_MASK = 1, EPI_GATE = 2 };

// ---------------- helpers --------------------------------------------------
__device__ __forceinline__ unsigned smem_cast(const void* p) {
    return (unsigned)__cvta_generic_to_shared(p);
}
__device__ __forceinline__ void cp16(unsigned dst, const void* src) {
    asm volatile("cp.async.cg.shared.global [%0], [%1], 16;" :: "r"(dst), "l"(src));
}
#define CP_COMMIT() asm volatile("cp.async.commit_group;")
#define CP_WAIT0()  asm volatile("cp.async.wait_group 0;")
#define CP_WAIT1()  asm volatile("cp.async.wait_group 1;")

__device__ __forceinline__ void ldsm_x4(unsigned* r, unsigned addr) {
    asm volatile("ldmatrix.sync.aligned.m8n8.x4.shared.b16 {%0,%1,%2,%3}, [%4];"
                 : "=r"(r[0]), "=r"(r[1]), "=r"(r[2]), "=r"(r[3]) : "r"(addr));
}
__device__ __forceinline__ void ldsm_x4_t(unsigned* r, unsigned addr) {
    asm volatile("ldmatrix.sync.aligned.m8n8.x4.trans.shared.b16 {%0,%1,%2,%3}, [%4];"
                 : "=r"(r[0]), "=r"(r[1]), "=r"(r[2]), "=r"(r[3]) : "r"(addr));
}
__device__ __forceinline__ void mma16816(float* c, const unsigned* a, const unsigned* b) {
    asm volatile("mma.sync.aligned.m16n8k16.row.col.f32.bf16.bf16.f32 "
                 "{%0,%1,%2,%3}, {%4,%5,%6,%7}, {%8,%9}, {%0,%1,%2,%3};"
                 : "+f"(c[0]), "+f"(c[1]), "+f"(c[2]), "+f"(c[3])
                 : "r"(a[0]), "r"(a[1]), "r"(a[2]), "r"(a[3]), "r"(b[0]), "r"(b[1]));
}
__device__ __forceinline__ void split3(float f, __nv_bfloat16& h, __nv_bfloat16& m,
                                       __nv_bfloat16& l) {
    h = __float2bfloat16(f);
    float r = f - __bfloat162float(h);
    m = __float2bfloat16(r);
    float r2 = r - __bfloat162float(m);
    l = __float2bfloat16(r2);
}

// ---------------- weight pre-split kernels ---------------------------------
__global__ void split3_kernel(const float* __restrict__ src,
                              __nv_bfloat16* __restrict__ H,
                              __nv_bfloat16* __restrict__ Mo,
                              __nv_bfloat16* __restrict__ L, int n4)
{
    int i = blockIdx.x * blockDim.x + threadIdx.x;
    if (i >= n4) return;
    float4 v = ((const float4*)src)[i];
    float f[4] = {v.x, v.y, v.z, v.w};
    __nv_bfloat16 h[4], m[4], l[4];
    #pragma unroll
    for (int q = 0; q < 4; q++) split3(f[q], h[q], m[q], l[q]);
    *(__nv_bfloat162*)&H[i * 4]     = __nv_bfloat162(h[0], h[1]);
    *(__nv_bfloat162*)&H[i * 4 + 2] = __nv_bfloat162(h[2], h[3]);
    *(__nv_bfloat162*)&Mo[i * 4]     = __nv_bfloat162(m[0], m[1]);
    *(__nv_bfloat162*)&Mo[i * 4 + 2] = __nv_bfloat162(m[2], m[3]);
    *(__nv_bfloat162*)&L[i * 4]     = __nv_bfloat162(l[0], l[1]);
    *(__nv_bfloat162*)&L[i * 4 + 2] = __nv_bfloat162(l[2], l[3]);
}

__global__ void split2_kernel(const float* __restrict__ src,
                              __nv_bfloat16* __restrict__ H,
                              __nv_bfloat16* __restrict__ L, int n4)
{
    int i = blockIdx.x * blockDim.x + threadIdx.x;
    if (i >= n4) return;
    float4 v = ((const float4*)src)[i];
    float f[4] = {v.x, v.y, v.z, v.w};
    __nv_bfloat16 h[4], l[4];
    #pragma unroll
    for (int q = 0; q < 4; q++) {
        h[q] = __float2bfloat16(f[q]);
        l[q] = __float2bfloat16(f[q] - __bfloat162float(h[q]));
    }
    *(__nv_bfloat162*)&H[i * 4]     = __nv_bfloat162(h[0], h[1]);
    *(__nv_bfloat162*)&H[i * 4 + 2] = __nv_bfloat162(h[2], h[3]);
    *(__nv_bfloat162*)&L[i * 4]     = __nv_bfloat162(l[0], l[1]);
    *(__nv_bfloat162*)&L[i * 4 + 2] = __nv_bfloat162(l[2], l[3]);
}

// ---------------------------------------------------------------------------
// Stages 1&2: blocked-compensated GEMM, 8x4 micro-tile (BM=128, BN=64).
// SAME k-structure as the 4x4 version (BK=16, SB=8 slabs, plain FMA within a
// slab, one TwoSum merge per slab) -> every C element sees the identical
// fp32 operation sequence -> bit-identical bx and masks.
// ---------------------------------------------------------------------------
template <int SB>
__global__ __launch_bounds__(256)
void comp_blk_gemm_kernel(const float* __restrict__ A, const float* __restrict__ B,
                          __nv_bfloat16* __restrict__ Ch,
                          __nv_bfloat16* __restrict__ Cm,
                          __nv_bfloat16* __restrict__ Cl,
                          int M, int N, int K,
                          const float* __restrict__ norm, float thresh)
{
    constexpr int BM = 128, BN = 64, BK = 16;
    static_assert(BK % SB == 0, "SB must divide BK");
    __shared__ float As[BK][BM];   // As[k][m]
    __shared__ float Bs[BK][BN];   // Bs[k][n]

    const int tid = threadIdx.x;
    const int m0 = blockIdx.y * BM;
    const int n0 = blockIdx.x * BN;
    const int ty = tid >> 4;       // 0..15, owns 8 rows
    const int tx = tid & 15;       // 0..15, owns 4 cols

    // A tile: 128x16 = 512 float4, 2/thread
    const int a_row = tid >> 2;          // 0..63 (and +64)
    const int a_col = (tid & 3) << 2;
    // B tile: 16x64 = 256 float4, 1/thread
    const int b_row = tid >> 4;          // 0..15
    const int b_col = (tid & 15) << 2;   // 0..60

    const float* Ap = A + (size_t)m0 * K;
    const float* Bp = B + n0;

    float hi[8][4], lo[8][4];
    #pragma unroll
    for (int i = 0; i < 8; i++)
        #pragma unroll
        for (int j = 0; j < 4; j++) { hi[i][j] = 0.0f; lo[i][j] = 0.0f; }

    for (int k0 = 0; k0 < K; k0 += BK) {
        float4 av0 = *(const float4*)(Ap + (size_t)a_row        * K + k0 + a_col);
        float4 av1 = *(const float4*)(Ap + (size_t)(a_row + 64) * K + k0 + a_col);
        float4 bv = *(const float4*)(Bp + (size_t)(k0 + b_row) * N + b_col);

        As[a_col + 0][a_row] = av0.x;
        As[a_col + 1][a_row] = av0.y;
        As[a_col + 2][a_row] = av0.z;
        As[a_col + 3][a_row] = av0.w;
        As[a_col + 0][a_row + 64] = av1.x;
        As[a_col + 1][a_row + 64] = av1.y;
        As[a_col + 2][a_row + 64] = av1.z;
        As[a_col + 3][a_row + 64] = av1.w;
        *(float4*)&Bs[b_row][b_col] = bv;
        __syncthreads();

        #pragma unroll
        for (int sb = 0; sb < BK / SB; sb++) {
            float blk[8][4];
            #pragma unroll
            for (int i = 0; i < 8; i++)
                #pragma unroll
                for (int j = 0; j < 4; j++) blk[i][j] = 0.0f;

            #pragma unroll
            for (int kk = sb * SB; kk < sb * SB + SB; kk++) {
                float a[8], b[4];
                *(float4*)&a[0] = *(const float4*)&As[kk][ty * 8];
                *(float4*)&a[4] = *(const float4*)&As[kk][ty * 8 + 4];
                *(float4*)&b[0] = *(const float4*)&Bs[kk][tx * 4];
                #pragma unroll
                for (int i = 0; i < 8; i++)
                    #pragma unroll
                    for (int j = 0; j < 4; j++)
                        blk[i][j] = __fmaf_rn(a[i], b[j], blk[i][j]);
            }

            // one error-free TwoSum merge per slab (same as before)
            #pragma unroll
            for (int i = 0; i < 8; i++) {
                #pragma unroll
                for (int j = 0; j < 4; j++) {
                    float p  = blk[i][j];
                    float t  = __fadd_rn(hi[i][j], p);
                    float bp = __fsub_rn(t, hi[i][j]);
                    float err = __fadd_rn(__fsub_rn(hi[i][j], __fsub_rn(t, bp)),
                                          __fsub_rn(p, bp));
                    hi[i][j] = t;
                    lo[i][j] = __fadd_rn(lo[i][j], err);
                }
            }
        }
        __syncthreads();
    }

    #pragma unroll
    for (int i = 0; i < 8; i++) {
        const int m = m0 + ty * 8 + i;
        const size_t row = (size_t)m * N + n0 + tx * 4;
        __nv_bfloat16 h[4], md[4], l[4];
        #pragma unroll
        for (int j = 0; j < 4; j++) {
            const int n = n0 + tx * 4 + j;
            float c = __fadd_rn(hi[i][j], lo[i][j]);
            c = (fabsf(c) * norm[n] > thresh) ? c : 0.0f;
            split3(c, h[j], md[j], l[j]);
        }
        *(__nv_bfloat162*)&Ch[row]     = __nv_bfloat162(h[0], h[1]);
        *(__nv_bfloat162*)&Ch[row + 2] = __nv_bfloat162(h[2], h[3]);
        *(__nv_bfloat162*)&Cm[row]     = __nv_bfloat162(md[0], md[1]);
        *(__nv_bfloat162*)&Cm[row + 2] = __nv_bfloat162(md[2], md[3]);
        *(__nv_bfloat162*)&Cl[row]     = __nv_bfloat162(l[0], l[1]);
        *(__nv_bfloat162*)&Cl[row + 2] = __nv_bfloat162(l[2], l[3]);
    }
}

// ---------------------------------------------------------------------------
// Stages 3&4: TC split-3 kernel, BN widened to 128 (warp tile 64x32).
// Per-accumulator mma order (hh; hm, mh, mm; lh, hl over the same k sequence)
// preserved -> bit-identical results.
// ---------------------------------------------------------------------------
#define LR_BK 32

struct LRBuf {
    __nv_bfloat16 Ah[128][LR_BK + 8];
    __nv_bfloat16 Am[128][LR_BK + 8];
    __nv_bfloat16 Al[128][LR_BK + 8];
    __nv_bfloat16 Bh[LR_BK][128 + 8];
    __nv_bfloat16 Bm[LR_BK][128 + 8];
    __nv_bfloat16 Bl[LR_BK][128 + 8];
};

template <int EPI>
__global__ __launch_bounds__(256, 1)
void lowrank_tc_kernel(const __nv_bfloat16* __restrict__ Ah_g,
                       const __nv_bfloat16* __restrict__ Am_g,
                       const __nv_bfloat16* __restrict__ Al_g,
                       const __nv_bfloat16* __restrict__ Bh_g,
                       const __nv_bfloat16* __restrict__ Bm_g,
                       const __nv_bfloat16* __restrict__ Bl_g,
                       float* __restrict__ C,
                       __nv_bfloat16* __restrict__ Hh,
                       __nv_bfloat16* __restrict__ Hl,
                       int M, int N, int K,
                       const float* __restrict__ norm, float thresh)
{
    extern __shared__ char smem_raw[];
    LRBuf* bufs = reinterpret_cast<LRBuf*>(smem_raw);

    const int tid  = threadIdx.x;
    const int wid  = tid >> 5;
    const int lane = tid & 31;

    const int tiles_n = N / 128;   // 86
    const int tiles_m = M / 128;   // 32
    const int group = 8;
    int bid = blockIdx.x;
    int gid = bid / (group * tiles_n);
    int first_m = gid * group;
    int rem = bid % (group * tiles_n);
    int gsz = min(group, tiles_m - first_m);
    int bm = first_m + rem % gsz;
    int bn = rem / gsz;

    const int warp_m = (wid >> 2) * 64;   // 0 or 64
    const int warp_n = (wid & 3) * 32;    // 0,32,64,96

    float acc_hi[4][4][4], acc_rest[4][4][4];
    #pragma unroll
    for (int i = 0; i < 4; i++)
        #pragma unroll
        for (int j = 0; j < 4; j++)
            #pragma unroll
            for (int q = 0; q < 4; q++) { acc_hi[i][j][q] = 0.0f; acc_rest[i][j][q] = 0.0f; }

    const int nk = K / LR_BK;

    auto issue_tile = [&](int kt, LRBuf& buf) {
        // A: 3 arrays, 128x32 bf16 = 512 16B-chunks -> 2/thread/array
        #pragma unroll
        for (int arr = 0; arr < 3; arr++) {
            const __nv_bfloat16* base =
                (arr == 0 ? Ah_g : arr == 1 ? Am_g : Al_g)
                + (size_t)(bm * 128) * K + kt * LR_BK;
            __nv_bfloat16 (*dst)[LR_BK + 8] =
                (arr == 0 ? buf.Ah : arr == 1 ? buf.Am : buf.Al);
            #pragma unroll
            for (int u = 0; u < 2; u++) {
                int id = tid + u * 256;
                int row = id >> 2, cc = id & 3;
                cp16(smem_cast(&dst[row][cc * 8]), base + (size_t)row * K + cc * 8);
            }
        }
        // B: 3 arrays, 32x128 bf16 = 512 chunks -> 2/thread/array
        #pragma unroll
        for (int arr = 0; arr < 3; arr++) {
            const __nv_bfloat16* base =
                (arr == 0 ? Bh_g : arr == 1 ? Bm_g : Bl_g)
                + (size_t)(kt * LR_BK) * N + bn * 128;
            __nv_bfloat16 (*dst)[128 + 8] =
                (arr == 0 ? buf.Bh : arr == 1 ? buf.Bm : buf.Bl);
            #pragma unroll
            for (int u = 0; u < 2; u++) {
                int id = tid + u * 256;
                int row = id >> 4, cc = id & 15;
                cp16(smem_cast(&dst[row][cc * 8]), base + (size_t)row * N + cc * 8);
            }
        }
    };

    issue_tile(0, bufs[0]);
    CP_COMMIT();

    for (int kt = 0; kt < nk; kt++) {
        LRBuf& cur = bufs[kt & 1];
        const bool more = (kt + 1 < nk);
        if (more) { issue_tile(kt + 1, bufs[(kt + 1) & 1]); CP_COMMIT(); }
        if (more) { CP_WAIT1(); } else { CP_WAIT0(); }
        __syncthreads();

        #pragma unroll
        for (int ks = 0; ks < 2; ks++) {
            const int k0 = ks * 16;
            unsigned fa[4][4], fa2[4][4], fb[2][4], fb2[2][4];

            const int arow = warp_m + (lane & 15);
            const int acol = k0 + (lane >> 4) * 8;
            const int brow = k0 + (lane & 7) + ((lane >> 3) & 1) * 8;

            #pragma unroll
            for (int mi = 0; mi < 4; mi++) ldsm_x4(fa[mi], smem_cast(&cur.Ah[arow + mi * 16][acol]));
            #pragma unroll
            for (int ng = 0; ng < 2; ng++)
                ldsm_x4_t(fb[ng], smem_cast(&cur.Bh[brow][warp_n + ng * 16 + (lane >> 4) * 8]));
            // h·h -> acc_hi
            #pragma unroll
            for (int mi = 0; mi < 4; mi++)
                #pragma unroll
                for (int nj = 0; nj < 4; nj++)
                    mma16816(acc_hi[mi][nj], fa[mi], &fb[nj >> 1][(nj & 1) * 2]);

            #pragma unroll
            for (int ng = 0; ng < 2; ng++)
                ldsm_x4_t(fb2[ng], smem_cast(&cur.Bm[brow][warp_n + ng * 16 + (lane >> 4) * 8]));
            #pragma unroll
            for (int mi = 0; mi < 4; mi++) ldsm_x4(fa2[mi], smem_cast(&cur.Am[arow + mi * 16][acol]));
            // h·m, m·h, m·m -> acc_rest
            #pragma unroll
            for (int mi = 0; mi < 4; mi++)
                #pragma unroll
                for (int nj = 0; nj < 4; nj++) {
                    mma16816(acc_rest[mi][nj], fa[mi],  &fb2[nj >> 1][(nj & 1) * 2]);
                    mma16816(acc_rest[mi][nj], fa2[mi], &fb[nj >> 1][(nj & 1) * 2]);
                    mma16816(acc_rest[mi][nj], fa2[mi], &fb2[nj >> 1][(nj & 1) * 2]);
                }

            #pragma unroll
            for (int mi = 0; mi < 4; mi++) ldsm_x4(fa2[mi], smem_cast(&cur.Al[arow + mi * 16][acol]));
            #pragma unroll
            for (int ng = 0; ng < 2; ng++)
                ldsm_x4_t(fb2[ng], smem_cast(&cur.Bl[brow][warp_n + ng * 16 + (lane >> 4) * 8]));
            // l·h, h·l -> acc_rest
            #pragma unroll
            for (int mi = 0; mi < 4; mi++)
                #pragma unroll
                for (int nj = 0; nj < 4; nj++) {
                    mma16816(acc_rest[mi][nj], fa2[mi], &fb[nj >> 1][(nj & 1) * 2]);
                    mma16816(acc_rest[mi][nj], fa[mi],  &fb2[nj >> 1][(nj & 1) * 2]);
                }
        }
        __syncthreads();
    }

    // Epilogue
    #pragma unroll
    for (int mi = 0; mi < 4; mi++) {
        #pragma unroll
        for (int nj = 0; nj < 4; nj++) {
            int m = bm * 128 + warp_m + mi * 16 + (lane >> 2);
            int n = bn * 128 + warp_n + nj * 8 + (lane & 3) * 2;
            #pragma unroll
            for (int half = 0; half < 2; half++) {
                const size_t idx = (size_t)(m + half * 8) * N + n;
                float c0 = __fadd_rn(acc_hi[mi][nj][half * 2 + 0], acc_rest[mi][nj][half * 2 + 0]);
                float c1 = __fadd_rn(acc_hi[mi][nj][half * 2 + 1], acc_rest[mi][nj][half * 2 + 1]);
                if (EPI == EPI_GATE) {
                    float2 u = *(const float2*)&C[idx];   // o_up
                    float s0 = c0 / (1.0f + expf(-c0));
                    float s1 = c1 / (1.0f + expf(-c1));
                    float v0 = s0 * u.x;
                    float v1 = s1 * u.y;
                    v0 = (fabsf(v0) * norm[n]     > thresh) ? v0 : 0.0f;
                    v1 = (fabsf(v1) * norm[n + 1] > thresh) ? v1 : 0.0f;
                    __nv_bfloat16 h0 = __float2bfloat16(v0);
                    __nv_bfloat16 h1 = __float2bfloat16(v1);
                    __nv_bfloat16 l0 = __float2bfloat16(v0 - __bfloat162float(h0));
                    __nv_bfloat16 l1 = __float2bfloat16(v1 - __bfloat162float(h1));
                    *(__nv_bfloat162*)&Hh[idx] = __nv_bfloat162(h0, h1);
                    *(__nv_bfloat162*)&Hl[idx] = __nv_bfloat162(l0, l1);
                } else {
                    *(float2*)&C[idx] = make_float2(c0, c1);
                }
            }
        }
    }
}

// ---------------------------------------------------------------------------
// GEMM 5: TC split-2; cp.async staging. Unchanged from R15.
// ---------------------------------------------------------------------------
#define G5_BK 32

struct G5Buf {
    __nv_bfloat16 Ahi[128][G5_BK + 8];
    __nv_bfloat16 Alo[128][G5_BK + 8];
    __nv_bfloat16 Bhi[G5_BK][128 + 8];
    __nv_bfloat16 Blo[G5_BK][128 + 8];
};

__global__ __launch_bounds__(256, 1)
void gemm5_tc_kernel(const __nv_bfloat16* __restrict__ Ah_g,
                     const __nv_bfloat16* __restrict__ Al_g,
                     const __nv_bfloat16* __restrict__ Bh_g,
                     const __nv_bfloat16* __restrict__ Bl_g,
                     float* __restrict__ C, int M, int N, int K)
{
    extern __shared__ char smem_raw[];
    G5Buf* bufs = reinterpret_cast<G5Buf*>(smem_raw);

    const int tid  = threadIdx.x;
    const int wid  = tid >> 5;
    const int lane = tid & 31;

    const int tiles_n = N / 128;
    const int tiles_m = M / 128;
    const int group = 8;
    int bid = blockIdx.x;
    int gid = bid / (group * tiles_n);
    int first_m = gid * group;
    int rem = bid % (group * tiles_n);
    int gsz = min(group, tiles_m - first_m);
    int bm = first_m + rem % gsz;
    int bn = rem / gsz;

    const int warp_m = (wid >> 2) * 64;
    const int warp_n = (wid & 3) * 32;

    float acc[4][4][4];
    #pragma unroll
    for (int i = 0; i < 4; i++)
        #pragma unroll
        for (int j = 0; j < 4; j++)
            #pragma unroll
            for (int q = 0; q < 4; q++) acc[i][j][q] = 0.0f;

    const int nk = K / G5_BK;

    auto issue_tile = [&](int kt, G5Buf& buf) {
        #pragma unroll
        for (int arr = 0; arr < 2; arr++) {
            const __nv_bfloat16* base = (arr == 0 ? Ah_g : Al_g)
                + (size_t)(bm * 128) * K + kt * G5_BK;
            __nv_bfloat16 (*dst)[G5_BK + 8] = (arr == 0 ? buf.Ahi : buf.Alo);
            #pragma unroll
            for (int u = 0; u < 2; u++) {
                int id = tid + u * 256;
                int row = id >> 2, cc = id & 3;
                cp16(smem_cast(&dst[row][cc * 8]), base + (size_t)row * K + cc * 8);
            }
        }
        #pragma unroll
        for (int arr = 0; arr < 2; arr++) {
            const __nv_bfloat16* base = (arr == 0 ? Bh_g : Bl_g)
                + (size_t)(kt * G5_BK) * N + bn * 128;
            __nv_bfloat16 (*dst)[128 + 8] = (arr == 0 ? buf.Bhi : buf.Blo);
            #pragma unroll
            for (int u = 0; u < 2; u++) {
                int id = tid + u * 256;
                int row = id >> 4, cc = id & 15;
                cp16(smem_cast(&dst[row][cc * 8]), base + (size_t)row * N + cc * 8);
            }
        }
    };

    issue_tile(0, bufs[0]);
    CP_COMMIT();

    for (int kt = 0; kt < nk; kt++) {
        G5Buf& cur = bufs[kt & 1];
        const bool more = (kt + 1 < nk);
        if (more) { issue_tile(kt + 1, bufs[(kt + 1) & 1]); CP_COMMIT(); }
        if (more) { CP_WAIT1(); } else { CP_WAIT0(); }
        __syncthreads();

        #pragma unroll
        for (int ks = 0; ks < 2; ks++) {
            unsigned ahi[4][4], alo[4][4], bhi[2][4], blo[2][4];
            const int k0 = ks * 16;
            #pragma unroll
            for (int mi = 0; mi < 4; mi++) {
                ldsm_x4(ahi[mi], smem_cast(&cur.Ahi[warp_m + mi * 16 + (lane & 15)][k0 + (lane >> 4) * 8]));
                ldsm_x4(alo[mi], smem_cast(&cur.Alo[warp_m + mi * 16 + (lane & 15)][k0 + (lane >> 4) * 8]));
            }
            #pragma unroll
            for (int ng = 0; ng < 2; ng++) {
                const int col = warp_n + ng * 16 + (lane >> 4) * 8;
                const int row = k0 + (lane & 7) + ((lane >> 3) & 1) * 8;
                ldsm_x4_t(bhi[ng], smem_cast(&cur.Bhi[row][col]));
                ldsm_x4_t(blo[ng], smem_cast(&cur.Blo[row][col]));
            }
            #pragma unroll
            for (int mi = 0; mi < 4; mi++) {
                #pragma unroll
                for (int nj = 0; nj < 4; nj++) {
                    const unsigned* bh = &bhi[nj >> 1][(nj & 1) * 2];
                    const unsigned* bl = &blo[nj >> 1][(nj & 1) * 2];
                    mma16816(acc[mi][nj], ahi[mi], bh);
                    mma16816(acc[mi][nj], ahi[mi], bl);
                    mma16816(acc[mi][nj], alo[mi], bh);
                }
            }
        }
        __syncthreads();
    }

    #pragma unroll
    for (int mi = 0; mi < 4; mi++) {
        #pragma unroll
        for (int nj = 0; nj < 4; nj++) {
            int m = bm * 128 + warp_m + mi * 16 + (lane >> 2);
            int n = bn * 128 + warp_n + nj * 8 + (lane & 3) * 2;
            *(float2*)&C[(size_t)m * N + n]       = make_float2(acc[mi][nj][0], acc[mi][nj][1]);
            *(float2*)&C[(size_t)(m + 8) * N + n] = make_float2(acc[mi][nj][2], acc[mi][nj][3]);
        }
    }
}

extern "C" void kernel_launch(void* const* d_in, const int* in_sizes, int n_in,
                              void* d_out, int out_size)
{
    const float* x         = (const float*)d_in[0];
    const float* B_up      = (const float*)d_in[1];
    const float* A_t_up    = (const float*)d_in[2];
    const float* B_gate    = (const float*)d_in[3];
    const float* A_t_gate  = (const float*)d_in[4];
    const float* b_norm_up   = (const float*)d_in[5];
    const float* b_norm_gate = (const float*)d_in[6];
    const float* w_norm_down = (const float*)d_in[7];
    const float* W_t_down  = (const float*)d_in[8];
    float* out = (float*)d_out;

    float* oup;
    cudaGetSymbolAddress((void**)&oup, g_oup);
    __nv_bfloat16 *bxu_h, *bxu_m, *bxu_l, *bxg_h, *bxg_m, *bxg_l;
    __nv_bfloat16 *atu_h, *atu_m, *atu_l, *atg_h, *atg_m, *atg_l;
    __nv_bfloat16 *wtd_hi, *wtd_lo, *hh, *hl;
    cudaGetSymbolAddress((void**)&bxu_h, g_bxu_h);
    cudaGetSymbolAddress((void**)&bxu_m, g_bxu_m);
    cudaGetSymbolAddress((void**)&bxu_l, g_bxu_l);
    cudaGetSymbolAddress((void**)&bxg_h, g_bxg_h);
    cudaGetSymbolAddress((void**)&bxg_m, g_bxg_m);
    cudaGetSymbolAddress((void**)&bxg_l, g_bxg_l);
    cudaGetSymbolAddress((void**)&atu_h, g_atu_h);
    cudaGetSymbolAddress((void**)&atu_m, g_atu_m);
    cudaGetSymbolAddress((void**)&atu_l, g_atu_l);
    cudaGetSymbolAddress((void**)&atg_h, g_atg_h);
    cudaGetSymbolAddress((void**)&atg_m, g_atg_m);
    cudaGetSymbolAddress((void**)&atg_l, g_atg_l);
    cudaGetSymbolAddress((void**)&wtd_hi, g_wtd_hi);
    cudaGetSymbolAddress((void**)&wtd_lo, g_wtd_lo);
    cudaGetSymbolAddress((void**)&hh, g_hh);
    cudaGetSymbolAddress((void**)&hl, g_hl);

    const int lr_smem = 2 * (int)sizeof(LRBuf);
    const int g5_smem = 2 * (int)sizeof(G5Buf);
    cudaFuncSetAttribute(lowrank_tc_kernel<EPI_NONE>,
                         cudaFuncAttributeMaxDynamicSharedMemorySize, lr_smem);
    cudaFuncSetAttribute(lowrank_tc_kernel<EPI_GATE>,
                         cudaFuncAttributeMaxDynamicSharedMemorySize, lr_smem);
    cudaFuncSetAttribute(gemm5_tc_kernel,
                         cudaFuncAttributeMaxDynamicSharedMemorySize, g5_smem);

    dim3 blk(256);

    // 0) pre-split weights
    {
        int n4 = R_DIM * DFF_DIM / 4;
        split3_kernel<<<(n4 + 255) / 256, 256>>>(A_t_up,   atu_h, atu_m, atu_l, n4);
        split3_kernel<<<(n4 + 255) / 256, 256>>>(A_t_gate, atg_h, atg_m, atg_l, n4);
        int n4w = DFF_DIM * D_DIM / 4;
        split2_kernel<<<(n4w + 255) / 256, 256>>>(W_t_down, wtd_hi, wtd_lo, n4w);
    }
    // 1) bxu = split3(mask_up(x @ B_up)) — exact blocked-comp, SB=8, 8x4 tile
    {
        dim3 grid(R_DIM / 64, S_DIM / 128);
        comp_blk_gemm_kernel<8><<<grid, blk>>>(x, B_up, bxu_h, bxu_m, bxu_l,
            S_DIM, R_DIM, D_DIM, b_norm_up, THRESH_UP);
    }
    // 2) bxg = split3(mask_gate(x @ B_gate))
    {
        dim3 grid(R_DIM / 64, S_DIM / 128);
        comp_blk_gemm_kernel<8><<<grid, blk>>>(x, B_gate, bxg_h, bxg_m, bxg_l,
            S_DIM, R_DIM, D_DIM, b_norm_gate, THRESH_GATE);
    }
    // 3) o_up = bxu @ A_t_up  (fp32 out) — TC split-3, BN=128
    {
        dim3 grid((S_DIM / 128) * (DFF_DIM / 128));
        lowrank_tc_kernel<EPI_NONE><<<grid, blk, lr_smem>>>(
            bxu_h, bxu_m, bxu_l, atu_h, atu_m, atu_l,
            oup, nullptr, nullptr, S_DIM, DFF_DIM, R_DIM, nullptr, 0.0f);
    }
    // 4) h = split2(mask_down(silu(bxg @ A_t_gate) * o_up)) — TC split-3, BN=128
    {
        dim3 grid((S_DIM / 128) * (DFF_DIM / 128));
        lowrank_tc_kernel<EPI_GATE><<<grid, blk, lr_smem>>>(
            bxg_h, bxg_m, bxg_l, atg_h, atg_m, atg_l,
            oup, hh, hl, S_DIM, DFF_DIM, R_DIM, w_norm_down, THRESH_DOWN);
    }
    // 5) out = h @ W_t_down
    {
        dim3 grid((S_DIM / 128) * (D_DIM / 128));
        gemm5_tc_kernel<<<grid, blk, g5_smem>>>(hh, hl, wtd_hi, wtd_lo,
            out, S_DIM, D_DIM, DFF_DIM);
    }
    (void)in_sizes; (void)n_in; (void)out_size;
}

// round 17
// speedup vs baseline: 1.7083x; 1.7083x over previous
#include <cuda_runtime.h>
#include <cuda_bf16.h>
#include <math.h>

#define S_DIM   4096
#define D_DIM   4096
#define R_DIM   1024
#define DFF_DIM 11008

#define THRESH_UP   0.4f
#define THRESH_GATE 0.4f
#define THRESH_DOWN 0.1f

// ---------------- device global scratch (allocation is banned) -------------
__device__ float g_oup[(size_t)S_DIM * DFF_DIM];                  // o_up fp32
__device__ __align__(16) __nv_bfloat16 g_bxu_h[(size_t)S_DIM * R_DIM];
__device__ __align__(16) __nv_bfloat16 g_bxu_m[(size_t)S_DIM * R_DIM];
__device__ __align__(16) __nv_bfloat16 g_bxu_l[(size_t)S_DIM * R_DIM];
__device__ __align__(16) __nv_bfloat16 g_bxg_h[(size_t)S_DIM * R_DIM];
__device__ __align__(16) __nv_bfloat16 g_bxg_m[(size_t)S_DIM * R_DIM];
__device__ __align__(16) __nv_bfloat16 g_bxg_l[(size_t)S_DIM * R_DIM];
__device__ __align__(16) __nv_bfloat16 g_atu_h[(size_t)R_DIM * DFF_DIM];
__device__ __align__(16) __nv_bfloat16 g_atu_m[(size_t)R_DIM * DFF_DIM];
__device__ __align__(16) __nv_bfloat16 g_atu_l[(size_t)R_DIM * DFF_DIM];
__device__ __align__(16) __nv_bfloat16 g_atg_h[(size_t)R_DIM * DFF_DIM];
__device__ __align__(16) __nv_bfloat16 g_atg_m[(size_t)R_DIM * DFF_DIM];
__device__ __align__(16) __nv_bfloat16 g_atg_l[(size_t)R_DIM * DFF_DIM];
__device__ __align__(16) __nv_bfloat16 g_wtd_hi[(size_t)DFF_DIM * D_DIM];
__device__ __align__(16) __nv_bfloat16 g_wtd_lo[(size_t)DFF_DIM * D_DIM];
__device__ __align__(16) __nv_bfloat16 g_hh[(size_t)S_DIM * DFF_DIM];
__device__ __align__(16) __nv_bfloat16 g_hl[(size_t)S_DIM * DFF_DIM];

enum { EPI_NONE = 0, EPI_MASK = 1, EPI_GATE = 2 };

// ---------------- helpers --------------------------------------------------
__device__ __forceinline__ unsigned smem_cast(const void* p) {
    return (unsigned)__cvta_generic_to_shared(p);
}
__device__ __forceinline__ void cp16(unsigned dst, const void* src) {
    asm volatile("cp.async.cg.shared.global [%0], [%1], 16;" :: "r"(dst), "l"(src));
}
#define CP_COMMIT() asm volatile("cp.async.commit_group;")
#define CP_WAIT0()  asm volatile("cp.async.wait_group 0;")
#define CP_WAIT1()  asm volatile("cp.async.wait_group 1;")

__device__ __forceinline__ void ldsm_x4(unsigned* r, unsigned addr) {
    asm volatile("ldmatrix.sync.aligned.m8n8.x4.shared.b16 {%0,%1,%2,%3}, [%4];"
                 : "=r"(r[0]), "=r"(r[1]), "=r"(r[2]), "=r"(r[3]) : "r"(addr));
}
__device__ __forceinline__ void ldsm_x4_t(unsigned* r, unsigned addr) {
    asm volatile("ldmatrix.sync.aligned.m8n8.x4.trans.shared.b16 {%0,%1,%2,%3}, [%4];"
                 : "=r"(r[0]), "=r"(r[1]), "=r"(r[2]), "=r"(r[3]) : "r"(addr));
}
__device__ __forceinline__ void mma16816(float* c, const unsigned* a, const unsigned* b) {
    asm volatile("mma.sync.aligned.m16n8k16.row.col.f32.bf16.bf16.f32 "
                 "{%0,%1,%2,%3}, {%4,%5,%6,%7}, {%8,%9}, {%0,%1,%2,%3};"
                 : "+f"(c[0]), "+f"(c[1]), "+f"(c[2]), "+f"(c[3])
                 : "r"(a[0]), "r"(a[1]), "r"(a[2]), "r"(a[3]), "r"(b[0]), "r"(b[1]));
}
__device__ __forceinline__ void split3(float f, __nv_bfloat16& h, __nv_bfloat16& m,
                                       __nv_bfloat16& l) {
    h = __float2bfloat16(f);
    float r = f - __bfloat162float(h);
    m = __float2bfloat16(r);
    float r2 = r - __bfloat162float(m);
    l = __float2bfloat16(r2);
}

// ---------------- weight pre-split kernels ---------------------------------
__global__ void split3_kernel(const float* __restrict__ src,
                              __nv_bfloat16* __restrict__ H,
                              __nv_bfloat16* __restrict__ Mo,
                              __nv_bfloat16* __restrict__ L, int n4)
{
    int i = blockIdx.x * blockDim.x + threadIdx.x;
    if (i >= n4) return;
    float4 v = ((const float4*)src)[i];
    float f[4] = {v.x, v.y, v.z, v.w};
    __nv_bfloat16 h[4], m[4], l[4];
    #pragma unroll
    for (int q = 0; q < 4; q++) split3(f[q], h[q], m[q], l[q]);
    *(__nv_bfloat162*)&H[i * 4]     = __nv_bfloat162(h[0], h[1]);
    *(__nv_bfloat162*)&H[i * 4 + 2] = __nv_bfloat162(h[2], h[3]);
    *(__nv_bfloat162*)&Mo[i * 4]     = __nv_bfloat162(m[0], m[1]);
    *(__nv_bfloat162*)&Mo[i * 4 + 2] = __nv_bfloat162(m[2], m[3]);
    *(__nv_bfloat162*)&L[i * 4]     = __nv_bfloat162(l[0], l[1]);
    *(__nv_bfloat162*)&L[i * 4 + 2] = __nv_bfloat162(l[2], l[3]);
}

__global__ void split2_kernel(const float* __restrict__ src,
                              __nv_bfloat16* __restrict__ H,
                              __nv_bfloat16* __restrict__ L, int n4)
{
    int i = blockIdx.x * blockDim.x + threadIdx.x;
    if (i >= n4) return;
    float4 v = ((const float4*)src)[i];
    float f[4] = {v.x, v.y, v.z, v.w};
    __nv_bfloat16 h[4], l[4];
    #pragma unroll
    for (int q = 0; q < 4; q++) {
        h[q] = __float2bfloat16(f[q]);
        l[q] = __float2bfloat16(f[q] - __bfloat162float(h[q]));
    }
    *(__nv_bfloat162*)&H[i * 4]     = __nv_bfloat162(h[0], h[1]);
    *(__nv_bfloat162*)&H[i * 4 + 2] = __nv_bfloat162(h[2], h[3]);
    *(__nv_bfloat162*)&L[i * 4]     = __nv_bfloat162(l[0], l[1]);
    *(__nv_bfloat162*)&L[i * 4 + 2] = __nv_bfloat162(l[2], l[3]);
}

// ---------------------------------------------------------------------------
// Stages 1&2: blocked-compensated GEMM (TwoSum merge), 4x4 tile (R15 config),
// now with DOUBLE-BUFFERED smem + register prefetch (one sync per k-tile).
// Arithmetic and order identical -> bit-identical bx and masks.
// Register budget: hi/lo/blk 48 + prefetch 8 + a/b 8 + idx ~ 100 -> 2 CTAs/SM.
// ---------------------------------------------------------------------------
template <int SB>
__global__ __launch_bounds__(256, 2)
void comp_blk_gemm_kernel(const float* __restrict__ A, const float* __restrict__ B,
                          __nv_bfloat16* __restrict__ Ch,
                          __nv_bfloat16* __restrict__ Cm,
                          __nv_bfloat16* __restrict__ Cl,
                          int M, int N, int K,
                          const float* __restrict__ norm, float thresh)
{
    constexpr int BM = 64, BN = 64, BK = 16;
    static_assert(BK % SB == 0, "SB must divide BK");
    __shared__ float As[2][BK][BM];   // As[buf][k][m]
    __shared__ float Bs[2][BK][BN];   // Bs[buf][k][n]

    const int tid = threadIdx.x;
    const int m0 = blockIdx.y * BM;
    const int n0 = blockIdx.x * BN;
    const int ty = tid >> 4;
    const int tx = tid & 15;

    const int a_row = tid >> 2;
    const int a_col = (tid & 3) << 2;
    const int b_row = tid >> 4;
    const int b_col = (tid & 15) << 2;

    const float* Ap = A + (size_t)m0 * K;
    const float* Bp = B + n0;

    float hi[4][4], lo[4][4];
    #pragma unroll
    for (int i = 0; i < 4; i++)
        #pragma unroll
        for (int j = 0; j < 4; j++) { hi[i][j] = 0.0f; lo[i][j] = 0.0f; }

    const int nk = K / BK;
    float4 av, bv;

    auto load_regs = [&](int kt) {
        av = *(const float4*)(Ap + (size_t)a_row * K + kt * BK + a_col);
        bv = *(const float4*)(Bp + (size_t)(kt * BK + b_row) * N + b_col);
    };
    auto store_buf = [&](int p) {
        As[p][a_col + 0][a_row] = av.x;
        As[p][a_col + 1][a_row] = av.y;
        As[p][a_col + 2][a_row] = av.z;
        As[p][a_col + 3][a_row] = av.w;
        *(float4*)&Bs[p][b_row][b_col] = bv;
    };

    load_regs(0);
    store_buf(0);
    __syncthreads();

    for (int kt = 0; kt < nk; kt++) {
        const int p = kt & 1;
        const bool more = (kt + 1 < nk);
        if (more) load_regs(kt + 1);   // global loads overlap compute

        #pragma unroll
        for (int sb = 0; sb < BK / SB; sb++) {
            float blk[4][4];
            #pragma unroll
            for (int i = 0; i < 4; i++)
                #pragma unroll
                for (int j = 0; j < 4; j++) blk[i][j] = 0.0f;

            #pragma unroll
            for (int kk = sb * SB; kk < sb * SB + SB; kk++) {
                float a[4], b[4];
                *(float4*)&a[0] = *(const float4*)&As[p][kk][ty * 4];
                *(float4*)&b[0] = *(const float4*)&Bs[p][kk][tx * 4];
                #pragma unroll
                for (int i = 0; i < 4; i++)
                    #pragma unroll
                    for (int j = 0; j < 4; j++)
                        blk[i][j] = __fmaf_rn(a[i], b[j], blk[i][j]);
            }

            #pragma unroll
            for (int i = 0; i < 4; i++) {
                #pragma unroll
                for (int j = 0; j < 4; j++) {
                    float pp = blk[i][j];
                    float t  = __fadd_rn(hi[i][j], pp);
                    float bp = __fsub_rn(t, hi[i][j]);
                    float err = __fadd_rn(__fsub_rn(hi[i][j], __fsub_rn(t, bp)),
                                          __fsub_rn(pp, bp));
                    hi[i][j] = t;
                    lo[i][j] = __fadd_rn(lo[i][j], err);
                }
            }
        }

        if (more) store_buf(p ^ 1);   // other buffer: no pre-store sync needed
        __syncthreads();
    }

    #pragma unroll
    for (int i = 0; i < 4; i++) {
        const int m = m0 + ty * 4 + i;
        const size_t row = (size_t)m * N + n0 + tx * 4;
        __nv_bfloat16 h[4], md[4], l[4];
        #pragma unroll
        for (int j = 0; j < 4; j++) {
            const int n = n0 + tx * 4 + j;
            float c = __fadd_rn(hi[i][j], lo[i][j]);
            c = (fabsf(c) * norm[n] > thresh) ? c : 0.0f;
            split3(c, h[j], md[j], l[j]);
        }
        *(__nv_bfloat162*)&Ch[row]     = __nv_bfloat162(h[0], h[1]);
        *(__nv_bfloat162*)&Ch[row + 2] = __nv_bfloat162(h[2], h[3]);
        *(__nv_bfloat162*)&Cm[row]     = __nv_bfloat162(md[0], md[1]);
        *(__nv_bfloat162*)&Cm[row + 2] = __nv_bfloat162(md[2], md[3]);
        *(__nv_bfloat162*)&Cl[row]     = __nv_bfloat162(l[0], l[1]);
        *(__nv_bfloat162*)&Cl[row + 2] = __nv_bfloat162(l[2], l[3]);
    }
}

// ---------------------------------------------------------------------------
// Stages 3&4: TC split-3 kernel, BN=64 (R15 config — fits registers),
// cp.async staging, double-buffered. Bit-identical mma order.
// ---------------------------------------------------------------------------
#define LR_BK 32

struct LRBuf {
    __nv_bfloat16 Ah[128][LR_BK + 8];
    __nv_bfloat16 Am[128][LR_BK + 8];
    __nv_bfloat16 Al[128][LR_BK + 8];
    __nv_bfloat16 Bh[LR_BK][64 + 8];
    __nv_bfloat16 Bm[LR_BK][64 + 8];
    __nv_bfloat16 Bl[LR_BK][64 + 8];
};

template <int EPI>
__global__ __launch_bounds__(256, 1)
void lowrank_tc_kernel(const __nv_bfloat16* __restrict__ Ah_g,
                       const __nv_bfloat16* __restrict__ Am_g,
                       const __nv_bfloat16* __restrict__ Al_g,
                       const __nv_bfloat16* __restrict__ Bh_g,
                       const __nv_bfloat16* __restrict__ Bm_g,
                       const __nv_bfloat16* __restrict__ Bl_g,
                       float* __restrict__ C,
                       __nv_bfloat16* __restrict__ Hh,
                       __nv_bfloat16* __restrict__ Hl,
                       int M, int N, int K,
                       const float* __restrict__ norm, float thresh)
{
    extern __shared__ char smem_raw[];
    LRBuf* bufs = reinterpret_cast<LRBuf*>(smem_raw);

    const int tid  = threadIdx.x;
    const int wid  = tid >> 5;
    const int lane = tid & 31;

    const int tiles_n = N / 64;
    const int tiles_m = M / 128;
    const int group = 8;
    int bid = blockIdx.x;
    int gid = bid / (group * tiles_n);
    int first_m = gid * group;
    int rem = bid % (group * tiles_n);
    int gsz = min(group, tiles_m - first_m);
    int bm = first_m + rem % gsz;
    int bn = rem / gsz;

    const int warp_m = (wid >> 2) * 64;
    const int warp_n = (wid & 3) * 16;

    float acc_hi[4][2][4], acc_rest[4][2][4];
    #pragma unroll
    for (int i = 0; i < 4; i++)
        #pragma unroll
        for (int j = 0; j < 2; j++)
            #pragma unroll
            for (int q = 0; q < 4; q++) { acc_hi[i][j][q] = 0.0f; acc_rest[i][j][q] = 0.0f; }

    const int nk = K / LR_BK;

    auto issue_tile = [&](int kt, LRBuf& buf) {
        #pragma unroll
        for (int arr = 0; arr < 3; arr++) {
            const __nv_bfloat16* base =
                (arr == 0 ? Ah_g : arr == 1 ? Am_g : Al_g)
                + (size_t)(bm * 128) * K + kt * LR_BK;
            __nv_bfloat16 (*dst)[LR_BK + 8] =
                (arr == 0 ? buf.Ah : arr == 1 ? buf.Am : buf.Al);
            #pragma unroll
            for (int u = 0; u < 2; u++) {
                int id = tid + u * 256;
                int row = id >> 2, cc = id & 3;
                cp16(smem_cast(&dst[row][cc * 8]), base + (size_t)row * K + cc * 8);
            }
        }
        #pragma unroll
        for (int arr = 0; arr < 3; arr++) {
            const __nv_bfloat16* base =
                (arr == 0 ? Bh_g : arr == 1 ? Bm_g : Bl_g)
                + (size_t)(kt * LR_BK) * N + bn * 64;
            __nv_bfloat16 (*dst)[64 + 8] =
                (arr == 0 ? buf.Bh : arr == 1 ? buf.Bm : buf.Bl);
            int row = tid >> 3, cc = tid & 7;
            cp16(smem_cast(&dst[row][cc * 8]), base + (size_t)row * N + cc * 8);
        }
    };

    issue_tile(0, bufs[0]);
    CP_COMMIT();

    for (int kt = 0; kt < nk; kt++) {
        LRBuf& cur = bufs[kt & 1];
        const bool more = (kt + 1 < nk);
        if (more) { issue_tile(kt + 1, bufs[(kt + 1) & 1]); CP_COMMIT(); }
        if (more) { CP_WAIT1(); } else { CP_WAIT0(); }
        __syncthreads();

        #pragma unroll
        for (int ks = 0; ks < 2; ks++) {
            const int k0 = ks * 16;
            unsigned fa[4][4], fa2[4][4], fb[4], fb2[4];

            const int arow = warp_m + (lane & 15);
            const int acol = k0 + (lane >> 4) * 8;
            const int bcol = warp_n + (lane >> 4) * 8;
            const int brow = k0 + (lane & 7) + ((lane >> 3) & 1) * 8;

            #pragma unroll
            for (int mi = 0; mi < 4; mi++) ldsm_x4(fa[mi], smem_cast(&cur.Ah[arow + mi * 16][acol]));
            ldsm_x4_t(fb, smem_cast(&cur.Bh[brow][bcol]));
            #pragma unroll
            for (int mi = 0; mi < 4; mi++)
                #pragma unroll
                for (int nj = 0; nj < 2; nj++)
                    mma16816(acc_hi[mi][nj], fa[mi], &fb[nj * 2]);

            ldsm_x4_t(fb2, smem_cast(&cur.Bm[brow][bcol]));
            #pragma unroll
            for (int mi = 0; mi < 4; mi++) ldsm_x4(fa2[mi], smem_cast(&cur.Am[arow + mi * 16][acol]));
            #pragma unroll
            for (int mi = 0; mi < 4; mi++)
                #pragma unroll
                for (int nj = 0; nj < 2; nj++) {
                    mma16816(acc_rest[mi][nj], fa[mi],  &fb2[nj * 2]);
                    mma16816(acc_rest[mi][nj], fa2[mi], &fb[nj * 2]);
                    mma16816(acc_rest[mi][nj], fa2[mi], &fb2[nj * 2]);
                }

            #pragma unroll
            for (int mi = 0; mi < 4; mi++) ldsm_x4(fa2[mi], smem_cast(&cur.Al[arow + mi * 16][acol]));
            ldsm_x4_t(fb2, smem_cast(&cur.Bl[brow][bcol]));
            #pragma unroll
            for (int mi = 0; mi < 4; mi++)
                #pragma unroll
                for (int nj = 0; nj < 2; nj++) {
                    mma16816(acc_rest[mi][nj], fa2[mi], &fb[nj * 2]);
                    mma16816(acc_rest[mi][nj], fa[mi],  &fb2[nj * 2]);
                }
        }
        __syncthreads();
    }

    // Epilogue
    #pragma unroll
    for (int mi = 0; mi < 4; mi++) {
        #pragma unroll
        for (int nj = 0; nj < 2; nj++) {
            int m = bm * 128 + warp_m + mi * 16 + (lane >> 2);
            int n = bn * 64 + warp_n + nj * 8 + (lane & 3) * 2;
            #pragma unroll
            for (int half = 0; half < 2; half++) {
                const size_t idx = (size_t)(m + half * 8) * N + n;
                float c0 = __fadd_rn(acc_hi[mi][nj][half * 2 + 0], acc_rest[mi][nj][half * 2 + 0]);
                float c1 = __fadd_rn(acc_hi[mi][nj][half * 2 + 1], acc_rest[mi][nj][half * 2 + 1]);
                if (EPI == EPI_GATE) {
                    float2 u = *(const float2*)&C[idx];   // o_up
                    float s0 = c0 / (1.0f + expf(-c0));
                    float s1 = c1 / (1.0f + expf(-c1));
                    float v0 = s0 * u.x;
                    float v1 = s1 * u.y;
                    v0 = (fabsf(v0) * norm[n]     > thresh) ? v0 : 0.0f;
                    v1 = (fabsf(v1) * norm[n + 1] > thresh) ? v1 : 0.0f;
                    __nv_bfloat16 h0 = __float2bfloat16(v0);
                    __nv_bfloat16 h1 = __float2bfloat16(v1);
                    __nv_bfloat16 l0 = __float2bfloat16(v0 - __bfloat162float(h0));
                    __nv_bfloat16 l1 = __float2bfloat16(v1 - __bfloat162float(h1));
                    *(__nv_bfloat162*)&Hh[idx] = __nv_bfloat162(h0, h1);
                    *(__nv_bfloat162*)&Hl[idx] = __nv_bfloat162(l0, l1);
                } else {
                    *(float2*)&C[idx] = make_float2(c0, c1);
                }
            }
        }
    }
}

// ---------------------------------------------------------------------------
// GEMM 5: TC split-2; cp.async staging. Unchanged (R15).
// ---------------------------------------------------------------------------
#define G5_BK 32

struct G5Buf {
    __nv_bfloat16 Ahi[128][G5_BK + 8];
    __nv_bfloat16 Alo[128][G5_BK + 8];
    __nv_bfloat16 Bhi[G5_BK][128 + 8];
    __nv_bfloat16 Blo[G5_BK][128 + 8];
};

__global__ __launch_bounds__(256, 1)
void gemm5_tc_kernel(const __nv_bfloat16* __restrict__ Ah_g,
                     const __nv_bfloat16* __restrict__ Al_g,
                     const __nv_bfloat16* __restrict__ Bh_g,
                     const __nv_bfloat16* __restrict__ Bl_g,
                     float* __restrict__ C, int M, int N, int K)
{
    extern __shared__ char smem_raw[];
    G5Buf* bufs = reinterpret_cast<G5Buf*>(smem_raw);

    const int tid  = threadIdx.x;
    const int wid  = tid >> 5;
    const int lane = tid & 31;

    const int tiles_n = N / 128;
    const int tiles_m = M / 128;
    const int group = 8;
    int bid = blockIdx.x;
    int gid = bid / (group * tiles_n);
    int first_m = gid * group;
    int rem = bid % (group * tiles_n);
    int gsz = min(group, tiles_m - first_m);
    int bm = first_m + rem % gsz;
    int bn = rem / gsz;

    const int warp_m = (wid >> 2) * 64;
    const int warp_n = (wid & 3) * 32;

    float acc[4][4][4];
    #pragma unroll
    for (int i = 0; i < 4; i++)
        #pragma unroll
        for (int j = 0; j < 4; j++)
            #pragma unroll
            for (int q = 0; q < 4; q++) acc[i][j][q] = 0.0f;

    const int nk = K / G5_BK;

    auto issue_tile = [&](int kt, G5Buf& buf) {
        #pragma unroll
        for (int arr = 0; arr < 2; arr++) {
            const __nv_bfloat16* base = (arr == 0 ? Ah_g : Al_g)
                + (size_t)(bm * 128) * K + kt * G5_BK;
            __nv_bfloat16 (*dst)[G5_BK + 8] = (arr == 0 ? buf.Ahi : buf.Alo);
            #pragma unroll
            for (int u = 0; u < 2; u++) {
                int id = tid + u * 256;
                int row = id >> 2, cc = id & 3;
                cp16(smem_cast(&dst[row][cc * 8]), base + (size_t)row * K + cc * 8);
            }
        }
        #pragma unroll
        for (int arr = 0; arr < 2; arr++) {
            const __nv_bfloat16* base = (arr == 0 ? Bh_g : Bl_g)
                + (size_t)(kt * G5_BK) * N + bn * 128;
            __nv_bfloat16 (*dst)[128 + 8] = (arr == 0 ? buf.Bhi : buf.Blo);
            #pragma unroll
            for (int u = 0; u < 2; u++) {
                int id = tid + u * 256;
                int row = id >> 4, cc = id & 15;
                cp16(smem_cast(&dst[row][cc * 8]), base + (size_t)row * N + cc * 8);
            }
        }
    };

    issue_tile(0, bufs[0]);
    CP_COMMIT();

    for (int kt = 0; kt < nk; kt++) {
        G5Buf& cur = bufs[kt & 1];
        const bool more = (kt + 1 < nk);
        if (more) { issue_tile(kt + 1, bufs[(kt + 1) & 1]); CP_COMMIT(); }
        if (more) { CP_WAIT1(); } else { CP_WAIT0(); }
        __syncthreads();

        #pragma unroll
        for (int ks = 0; ks < 2; ks++) {
            unsigned ahi[4][4], alo[4][4], bhi[2][4], blo[2][4];
            const int k0 = ks * 16;
            #pragma unroll
            for (int mi = 0; mi < 4; mi++) {
                ldsm_x4(ahi[mi], smem_cast(&cur.Ahi[warp_m + mi * 16 + (lane & 15)][k0 + (lane >> 4) * 8]));
                ldsm_x4(alo[mi], smem_cast(&cur.Alo[warp_m + mi * 16 + (lane & 15)][k0 + (lane >> 4) * 8]));
            }
            #pragma unroll
            for (int ng = 0; ng < 2; ng++) {
                const int col = warp_n + ng * 16 + (lane >> 4) * 8;
                const int row = k0 + (lane & 7) + ((lane >> 3) & 1) * 8;
                ldsm_x4_t(bhi[ng], smem_cast(&cur.Bhi[row][col]));
                ldsm_x4_t(blo[ng], smem_cast(&cur.Blo[row][col]));
            }
            #pragma unroll
            for (int mi = 0; mi < 4; mi++) {
                #pragma unroll
                for (int nj = 0; nj < 4; nj++) {
                    const unsigned* bh = &bhi[nj >> 1][(nj & 1) * 2];
                    const unsigned* bl = &blo[nj >> 1][(nj & 1) * 2];
                    mma16816(acc[mi][nj], ahi[mi], bh);
                    mma16816(acc[mi][nj], ahi[mi], bl);
                    mma16816(acc[mi][nj], alo[mi], bh);
                }
            }
        }
        __syncthreads();
    }

    #pragma unroll
    for (int mi = 0; mi < 4; mi++) {
        #pragma unroll
        for (int nj = 0; nj < 4; nj++) {
            int m = bm * 128 + warp_m + mi * 16 + (lane >> 2);
            int n = bn * 128 + warp_n + nj * 8 + (lane & 3) * 2;
            *(float2*)&C[(size_t)m * N + n]       = make_float2(acc[mi][nj][0], acc[mi][nj][1]);
            *(float2*)&C[(size_t)(m + 8) * N + n] = make_float2(acc[mi][nj][2], acc[mi][nj][3]);
        }
    }
}

extern "C" void kernel_launch(void* const* d_in, const int* in_sizes, int n_in,
                              void* d_out, int out_size)
{
    const float* x         = (const float*)d_in[0];
    const float* B_up      = (const float*)d_in[1];
    const float* A_t_up    = (const float*)d_in[2];
    const float* B_gate    = (const float*)d_in[3];
    const float* A_t_gate  = (const float*)d_in[4];
    const float* b_norm_up   = (const float*)d_in[5];
    const float* b_norm_gate = (const float*)d_in[6];
    const float* w_norm_down = (const float*)d_in[7];
    const float* W_t_down  = (const float*)d_in[8];
    float* out = (float*)d_out;

    float* oup;
    cudaGetSymbolAddress((void**)&oup, g_oup);
    __nv_bfloat16 *bxu_h, *bxu_m, *bxu_l, *bxg_h, *bxg_m, *bxg_l;
    __nv_bfloat16 *atu_h, *atu_m, *atu_l, *atg_h, *atg_m, *atg_l;
    __nv_bfloat16 *wtd_hi, *wtd_lo, *hh, *hl;
    cudaGetSymbolAddress((void**)&bxu_h, g_bxu_h);
    cudaGetSymbolAddress((void**)&bxu_m, g_bxu_m);
    cudaGetSymbolAddress((void**)&bxu_l, g_bxu_l);
    cudaGetSymbolAddress((void**)&bxg_h, g_bxg_h);
    cudaGetSymbolAddress((void**)&bxg_m, g_bxg_m);
    cudaGetSymbolAddress((void**)&bxg_l, g_bxg_l);
    cudaGetSymbolAddress((void**)&atu_h, g_atu_h);
    cudaGetSymbolAddress((void**)&atu_m, g_atu_m);
    cudaGetSymbolAddress((void**)&atu_l, g_atu_l);
    cudaGetSymbolAddress((void**)&atg_h, g_atg_h);
    cudaGetSymbolAddress((void**)&atg_m, g_atg_m);
    cudaGetSymbolAddress((void**)&atg_l, g_atg_l);
    cudaGetSymbolAddress((void**)&wtd_hi, g_wtd_hi);
    cudaGetSymbolAddress((void**)&wtd_lo, g_wtd_lo);
    cudaGetSymbolAddress((void**)&hh, g_hh);
    cudaGetSymbolAddress((void**)&hl, g_hl);

    const int lr_smem = 2 * (int)sizeof(LRBuf);
    const int g5_smem = 2 * (int)sizeof(G5Buf);
    cudaFuncSetAttribute(lowrank_tc_kernel<EPI_NONE>,
                         cudaFuncAttributeMaxDynamicSharedMemorySize, lr_smem);
    cudaFuncSetAttribute(lowrank_tc_kernel<EPI_GATE>,
                         cudaFuncAttributeMaxDynamicSharedMemorySize, lr_smem);
    cudaFuncSetAttribute(gemm5_tc_kernel,
                         cudaFuncAttributeMaxDynamicSharedMemorySize, g5_smem);

    dim3 blk(256);

    // 0) pre-split weights
    {
        int n4 = R_DIM * DFF_DIM / 4;
        split3_kernel<<<(n4 + 255) / 256, 256>>>(A_t_up,   atu_h, atu_m, atu_l, n4);
        split3_kernel<<<(n4 + 255) / 256, 256>>>(A_t_gate, atg_h, atg_m, atg_l, n4);
        int n4w = DFF_DIM * D_DIM / 4;
        split2_kernel<<<(n4w + 255) / 256, 256>>>(W_t_down, wtd_hi, wtd_lo, n4w);
    }
    // 1) bxu = split3(mask_up(x @ B_up)) — exact blocked-comp, SB=8, 4x4, dbuf
    {
        dim3 grid(R_DIM / 64, S_DIM / 64);
        comp_blk_gemm_kernel<8><<<grid, blk>>>(x, B_up, bxu_h, bxu_m, bxu_l,
            S_DIM, R_DIM, D_DIM, b_norm_up, THRESH_UP);
    }
    // 2) bxg = split3(mask_gate(x @ B_gate))
    {
        dim3 grid(R_DIM / 64, S_DIM / 64);
        comp_blk_gemm_kernel<8><<<grid, blk>>>(x, B_gate, bxg_h, bxg_m, bxg_l,
            S_DIM, R_DIM, D_DIM, b_norm_gate, THRESH_GATE);
    }
    // 3) o_up = bxu @ A_t_up  (fp32 out) — TC split-3, BN=64
    {
        dim3 grid((S_DIM / 128) * (DFF_DIM / 64));
        lowrank_tc_kernel<EPI_NONE><<<grid, blk, lr_smem>>>(
            bxu_h, bxu_m, bxu_l, atu_h, atu_m, atu_l,
            oup, nullptr, nullptr, S_DIM, DFF_DIM, R_DIM, nullptr, 0.0f);
    }
    // 4) h = split2(mask_down(silu(bxg @ A_t_gate) * o_up)) — TC split-3, BN=64
    {
        dim3 grid((S_DIM / 128) * (DFF_DIM / 64));
        lowrank_tc_kernel<EPI_GATE><<<grid, blk, lr_smem>>>(
            bxg_h, bxg_m, bxg_l, atg_h, atg_m, atg_l,
            oup, hh, hl, S_DIM, DFF_DIM, R_DIM, w_norm_down, THRESH_DOWN);
    }
    // 5) out = h @ W_t_down
    {
        dim3 grid((S_DIM / 128) * (D_DIM / 128));
        gemm5_tc_kernel<<<grid, blk, g5_smem>>>(hh, hl, wtd_hi, wtd_lo,
            out, S_DIM, D_DIM, DFF_DIM);
    }
    (void)in_sizes; (void)n_in; (void)out_size;
}